// round 16
// baseline (speedup 1.0000x reference)
#include <cuda_runtime.h>
#include <cstdint>

#define BB 64
#define SS 512
#define HH 768
#define CC 9
#define QB 4         // blocks per batch
#define BW 8         // warps per block
#define KCH 32       // chunks per batch (1 per warp)
#define CH 16        // steps per chunk (32*16 = 512 >= 511)
#define L2E 1.4426950408889634f
#define LN2 0.6931471805599453f
#define FULLMASK 0xffffffffu

// scratch (no allocations allowed)
__device__ __align__(16) float g_P[BB * KCH * 81];   // chunk matrices
__device__ int   g_E[BB * KCH * CC];                 // per-row exponents
__device__ float g_num[BB * KCH];                    // numerator partials
__device__ float g_emis0[BB * CC];                   // t=0 emissions
__device__ int   g_bar[BB];                          // per-batch arrivals
__device__ float g_acc = 0.0f;
__device__ int   g_cnt = 0;

__device__ __forceinline__ float ex2f(float x) {
    float y; asm("ex2.approx.ftz.f32 %0, %1;" : "=f"(y) : "f"(x)); return y;
}
__device__ __forceinline__ float lg2f(float x) {
    float y; asm("lg2.approx.ftz.f32 %0, %1;" : "=f"(y) : "f"(x)); return y;
}
// packed f32x2 helpers (FFMA2 — only reachable via PTX)
__device__ __forceinline__ void fma2(unsigned long long& acc,
                                     unsigned long long a, unsigned long long b) {
    asm("fma.rn.f32x2 %0, %1, %2, %3;" : "=l"(acc) : "l"(a), "l"(b), "l"(acc));
}
__device__ __forceinline__ unsigned long long packdup(float x) {
    unsigned long long r;
    asm("mov.b64 %0, {%1, %1};" : "=l"(r) : "f"(x));
    return r;
}
__device__ __forceinline__ void unpack2(float& lo, float& hi, unsigned long long v) {
    asm("mov.b64 {%0, %1}, %2;" : "=f"(lo), "=f"(hi) : "l"(v));
}

// ---------------------------------------------------------------------------
// ONE kernel: grid (QB, BB) x 256. Block (q, b): 8 warps; warp w owns window
// k = q*8+w, timesteps [1+16k, 17+16k). Each warp: GEMV its 16 rows (FFMA2
// class-pair packing) -> smem, exp -> smem, numerator partial, 16-step chunk
// matrix product -> gmem. Last block per batch combines + atomic mean.
// ---------------------------------------------------------------------------
__global__ __launch_bounds__(256, 2) void crf_fused_kernel(
    const float* __restrict__ hidden,
    const float* __restrict__ W,
    const float* __restrict__ bias,
    const float* __restrict__ stv,
    const float* __restrict__ trv,
    const float* __restrict__ etv,
    const int*   __restrict__ tags,
    const int*   __restrict__ mask,
    float* __restrict__ out)
{
    __shared__ alignas(16) float2 Wz[4 * HH];         // zipped class pairs, 24576 B
    __shared__ alignas(16) float  W8[HH];             // class 8, 3072 B
    __shared__ alignas(16) union {
        struct {                                      // phase 1
            float raw[BW][CH * 12];                   // 6144 B raw emissions
            float eml[BW][CH * 12];                   // 6144 B exp(emissions)
        } p1;
        struct {                                      // phase 2 (combine blk)
            float P[KCH * 81];                        // 10368 B
            int   E[KCH * CC];                        // 1152 B
            int   Emax[KCH];                          // 128 B
        } p2;
    } u;
    __shared__ alignas(16) float Te_sm[CC][12];
    __shared__ float tr_sh[81];
    __shared__ float bias_sm[CC];
    __shared__ int   iam_last;

    const int q    = blockIdx.x;
    const int b    = blockIdx.y;
    const int tid  = threadIdx.x;
    const int wid  = tid >> 5;
    const int lane = tid & 31;
    const int k    = q * BW + wid;        // chunk/window id 0..31
    const int t0   = 1 + CH * k;          // first timestep of window

    // build zipped W (pairs of classes) + scalar class 8
    for (int idx = tid; idx < 4 * HH; idx += 256) {
        const int p = idx / HH, kk = idx - p * HH;
        Wz[idx] = make_float2(W[(2 * p) * HH + kk], W[(2 * p + 1) * HH + kk]);
    }
    for (int idx = tid; idx < HH; idx += 256) W8[idx] = W[8 * HH + idx];
    if (tid < 81) {
        const float t = trv[tid];
        tr_sh[tid] = t;
        Te_sm[tid / 9][tid % 9] = ex2f(t * L2E);
    }
    if (tid < CC) bias_sm[tid] = bias[tid];
    __syncthreads();

    // sequence length (mask is a prefix of ones)
    int len = 0;
    {
        const int* mrow = mask + (size_t)b * SS;
        for (int t = lane; t < SS; t += 32) len += mrow[t];
#pragma unroll
        for (int off = 16; off > 0; off >>= 1)
            len += __shfl_xor_sync(FULLMASK, len, off);
    }

    // ---- GEMV: 16 rows (+ t=0 extra group for q==0,wid==0) ----
    const int ngroups = (q == 0 && wid == 0) ? 5 : 4;
#pragma unroll 1
    for (int g = 0; g < ngroups; g++) {
        const int rbase = (g < 4) ? (t0 + 4 * g) : 0;
        const int r0 = (rbase + 0 < SS) ? rbase + 0 : SS - 1;
        const int r1 = (rbase + 1 < SS) ? rbase + 1 : SS - 1;
        const int r2 = (rbase + 2 < SS) ? rbase + 2 : SS - 1;
        const int r3 = (rbase + 3 < SS) ? rbase + 3 : SS - 1;
        const float4* hp0 = (const float4*)(hidden + ((size_t)b * SS + r0) * HH);
        const float4* hp1 = (const float4*)(hidden + ((size_t)b * SS + r1) * HH);
        const float4* hp2 = (const float4*)(hidden + ((size_t)b * SS + r2) * HH);
        const float4* hp3 = (const float4*)(hidden + ((size_t)b * SS + r3) * HH);

        unsigned long long acc2[4][4];   // [row][class-pair], f32x2
        float acc8[4];
        const unsigned long long z = packdup(0.0f);
#pragma unroll
        for (int r = 0; r < 4; r++) {
#pragma unroll
            for (int p = 0; p < 4; p++) acc2[r][p] = z;
            acc8[r] = 0.0f;
        }

#pragma unroll 2
        for (int i = 0; i < HH / 128; i++) {   // 6 iterations, 4 k-elems each
            float4 h[4];
            h[0] = hp0[i * 32 + lane];
            h[1] = hp1[i * 32 + lane];
            h[2] = hp2[i * 32 + lane];
            h[3] = hp3[i * 32 + lane];
            const int kbase = i * 128 + lane * 4;

            unsigned long long hd[4][4];
#pragma unroll
            for (int r = 0; r < 4; r++) {
                hd[r][0] = packdup(h[r].x);
                hd[r][1] = packdup(h[r].y);
                hd[r][2] = packdup(h[r].z);
                hd[r][3] = packdup(h[r].w);
            }
#pragma unroll
            for (int p = 0; p < 4; p++) {
                const ulonglong2 wA = *(const ulonglong2*)(Wz + p * HH + kbase);
                const ulonglong2 wB = *(const ulonglong2*)(Wz + p * HH + kbase + 2);
#pragma unroll
                for (int r = 0; r < 4; r++) {
                    fma2(acc2[r][p], hd[r][0], wA.x);
                    fma2(acc2[r][p], hd[r][1], wA.y);
                    fma2(acc2[r][p], hd[r][2], wB.x);
                    fma2(acc2[r][p], hd[r][3], wB.y);
                }
            }
            const float4 w8 = *(const float4*)(W8 + kbase);
#pragma unroll
            for (int r = 0; r < 4; r++) {
                acc8[r] = fmaf(h[r].x, w8.x, acc8[r]);
                acc8[r] = fmaf(h[r].y, w8.y, acc8[r]);
                acc8[r] = fmaf(h[r].z, w8.z, acc8[r]);
                acc8[r] = fmaf(h[r].w, w8.w, acc8[r]);
            }
        }

        // unpack to scalar accumulators, then butterfly reduce
        float acc[4][CC];
#pragma unroll
        for (int r = 0; r < 4; r++) {
#pragma unroll
            for (int p = 0; p < 4; p++)
                unpack2(acc[r][2 * p], acc[r][2 * p + 1], acc2[r][p]);
            acc[r][8] = acc8[r];
        }
#pragma unroll
        for (int r = 0; r < 4; r++)
#pragma unroll
            for (int c = 0; c < CC; c++)
#pragma unroll
                for (int off = 16; off > 0; off >>= 1)
                    acc[r][c] += __shfl_xor_sync(FULLMASK, acc[r][c], off);

        if (lane == 0) {
            if (g < 4) {
#pragma unroll
                for (int r = 0; r < 4; r++)
#pragma unroll
                    for (int c = 0; c < CC; c++)
                        u.p1.raw[wid][(4 * g + r) * 12 + c] = acc[r][c] + bias_sm[c];
            } else {
#pragma unroll
                for (int c = 0; c < CC; c++)
                    g_emis0[b * CC + c] = acc[0][c] + bias_sm[c];
            }
        }
    }
    __syncwarp();

    // ---- exponentiate emissions (spread across lanes) ----
    for (int idx = lane; idx < CH * CC; idx += 32) {
        const int row = idx / CC;
        const int cc  = idx - row * CC;
        u.p1.eml[wid][row * 12 + cc] = ex2f(u.p1.raw[wid][row * 12 + cc] * L2E);
    }
    __syncwarp();

    // ---- numerator partial over [t0, t0+16) ----
    float np = 0.0f;
    if (lane < CH) {
        const int t = t0 + lane;
        if (t < len) {
            const int tp = tags[(size_t)b * SS + t - 1];
            const int tc = tags[(size_t)b * SS + t];
            np = tr_sh[tp * CC + tc] + u.p1.raw[wid][lane * 12 + tc];
        }
    }
#pragma unroll
    for (int off = 16; off > 0; off >>= 1)
        np += __shfl_xor_sync(FULLMASK, np, off);
    if (lane == 0) g_num[b * KCH + k] = np;

    // ---- chunk matrix product: lane r < 9 holds row r of M ----
    const int r = (lane < CC) ? lane : 8;
    float m[CC];
#pragma unroll
    for (int c = 0; c < CC; c++) m[c] = (c == r) ? 1.0f : 0.0f;
    int esum = 0;

#pragma unroll 1
    for (int i = 0; i < CH; i++) {
        if (t0 + i >= len) break;
        const float* emlrow = &u.p1.eml[wid][i * 12];
        const float4 e0 = *(const float4*)&emlrow[0];
        const float4 e1 = *(const float4*)&emlrow[4];
        const float  e8 = emlrow[8];

        float v[CC];
#pragma unroll
        for (int c = 0; c < CC; c++) v[c] = 0.0f;
#pragma unroll
        for (int j = 0; j < CC; j++) {
            const float4 ta = *(const float4*)&Te_sm[j][0];
            const float4 tb2 = *(const float4*)&Te_sm[j][4];
            const float  t8 = Te_sm[j][8];
            const float  mj = m[j];
            v[0] = fmaf(mj, ta.x, v[0]); v[1] = fmaf(mj, ta.y, v[1]);
            v[2] = fmaf(mj, ta.z, v[2]); v[3] = fmaf(mj, ta.w, v[3]);
            v[4] = fmaf(mj, tb2.x, v[4]); v[5] = fmaf(mj, tb2.y, v[5]);
            v[6] = fmaf(mj, tb2.z, v[6]); v[7] = fmaf(mj, tb2.w, v[7]);
            v[8] = fmaf(mj, t8, v[8]);
        }
        v[0] *= e0.x; v[1] *= e0.y; v[2] *= e0.z; v[3] *= e0.w;
        v[4] *= e1.x; v[5] *= e1.y; v[6] *= e1.z; v[7] *= e1.w;
        v[8] *= e8;

        float mx01 = fmaxf(v[0], v[1]), mx23 = fmaxf(v[2], v[3]);
        float mx45 = fmaxf(v[4], v[5]), mx67 = fmaxf(v[6], v[7]);
        float mx = fmaxf(fmaxf(fmaxf(mx01, mx23), fmaxf(mx45, mx67)), v[8]);
        const int   eb  = (__float_as_int(mx) >> 23) & 0xff;
        const float pot = __int_as_float((254 - eb) << 23);
#pragma unroll
        for (int c = 0; c < CC; c++) m[c] = v[c] * pot;
        esum += eb - 127;
    }

    if (lane < CC) {
        float* dst = g_P + ((size_t)b * KCH + k) * 81 + r * 9;
#pragma unroll
        for (int c = 0; c < CC; c++) dst[c] = m[c];
        g_E[((size_t)b * KCH + k) * CC + r] = esum;
    }
    __syncthreads();

    // ---- arrival: last of the QB blocks for this batch combines ----
    if (tid == 0) {
        __threadfence();
        iam_last = (atomicAdd(&g_bar[b], 1) == QB - 1);
    }
    __syncthreads();
    if (!iam_last) return;
    if (tid == 0) __threadfence();   // acquire peers' writes
    __syncthreads();

    // ---- stage all 32 chunk matrices + exponents into smem ----
    for (int i = tid; i < KCH * 81 / 4; i += 256)
        ((float4*)u.p2.P)[i] = ((const float4*)(g_P + (size_t)b * KCH * 81))[i];
    for (int i = tid; i < KCH * CC; i += 256)
        u.p2.E[i] = g_E[(size_t)b * KCH * CC + i];
    __syncthreads();
    if (tid < KCH) {
        int e = u.p2.E[tid * CC];
#pragma unroll
        for (int r2 = 1; r2 < CC; r2++) e = max(e, u.p2.E[tid * CC + r2]);
        u.p2.Emax[tid] = e;
    }
    __syncthreads();
    if (wid != 0) return;

    // ---- combine (warp 0): a unnormalized, true alpha = a * 2^Etot ----
    const int  c  = (lane < CC) ? lane : 0;
    const bool on = (lane < CC);
    float a = on ? ex2f((stv[c] + g_emis0[b * CC + c]) * L2E) : 0.0f;
    int Etot = 0;

#pragma unroll 1
    for (int kk = 0; kk < KCH; kk++) {
        if (1 + kk * CH >= len) break;   // identity chunks beyond len

        const int emk = u.p2.Emax[kk];
        const int ej  = on ? u.p2.E[kk * CC + lane] : emk;
        const int d   = ej - emk;        // <= 0
        const float asc = (d > -126) ? a * __int_as_float((d + 127) << 23) : 0.0f;

        const float s0 = __shfl_sync(FULLMASK, asc, 0);
        const float s1 = __shfl_sync(FULLMASK, asc, 1);
        const float s2 = __shfl_sync(FULLMASK, asc, 2);
        const float s3 = __shfl_sync(FULLMASK, asc, 3);
        const float s4 = __shfl_sync(FULLMASK, asc, 4);
        const float s5 = __shfl_sync(FULLMASK, asc, 5);
        const float s6 = __shfl_sync(FULLMASK, asc, 6);
        const float s7 = __shfl_sync(FULLMASK, asc, 7);
        const float s8 = __shfl_sync(FULLMASK, asc, 8);

        const int   e0 = (((__float_as_int(s0) >> 23) & 0xff)) - 127;
        const float sc = __int_as_float((127 - e0) << 23);   // 2^{-e0}

        const float* Pk = u.p2.P + kk * 81;
        float p0 = s0 * Pk[0 * 9 + c], p1 = s1 * Pk[1 * 9 + c];
        float p2 = s2 * Pk[2 * 9 + c], p3 = s3 * Pk[3 * 9 + c];
        float p4 = s4 * Pk[4 * 9 + c], p5 = s5 * Pk[5 * 9 + c];
        float p6 = s6 * Pk[6 * 9 + c], p7 = s7 * Pk[7 * 9 + c];
        float p8 = s8 * Pk[8 * 9 + c];
        float q0 = p0 + p1, q1 = p2 + p3, q2 = p4 + p5, q3 = p6 + p7;
        const float na = ((q0 + q1) + (q2 + q3)) + p8;

        a = on ? na * sc : 0.0f;
        Etot += emk + e0;
    }

    // ---- denominator ----
    float term = on ? a * ex2f(etv[c] * L2E) : 0.0f;
#pragma unroll
    for (int off = 16; off > 0; off >>= 1)
        term += __shfl_xor_sync(FULLMASK, term, off);
    const float denom = (lg2f(term) + (float)Etot) * LN2;

    // ---- numerator assembly (32 partials = full warp) ----
    float nsum = g_num[b * KCH + lane];
#pragma unroll
    for (int off = 16; off > 0; off >>= 1)
        nsum += __shfl_xor_sync(FULLMASK, nsum, off);
    const int first = tags[(size_t)b * SS];
    const int last  = tags[(size_t)b * SS + len - 1];
    const float num = nsum + stv[first] + g_emis0[b * CC + first] + etv[last];
    const float llh = num - denom;

    if (lane == 0) {
        g_bar[b] = 0;   // reset for next graph replay
        atomicAdd(&g_acc, llh);
        __threadfence();
        const int cnt = atomicAdd(&g_cnt, 1);
        if (cnt == BB - 1) {
            __threadfence();
            const float total = atomicAdd(&g_acc, 0.0f);
            out[0] = -total * (1.0f / (float)BB);
            g_acc = 0.0f;
            g_cnt = 0;
        }
    }
}

// ---------------------------------------------------------------------------
extern "C" void kernel_launch(void* const* d_in, const int* in_sizes, int n_in,
                              void* d_out, int out_size)
{
    (void)in_sizes; (void)n_in; (void)out_size;
    const float* hidden = (const float*)d_in[0];
    const float* W      = (const float*)d_in[1];
    const float* bias   = (const float*)d_in[2];
    const float* stv    = (const float*)d_in[3];
    const float* trv    = (const float*)d_in[4];
    const float* etv    = (const float*)d_in[5];
    const int*   tags   = (const int*)d_in[6];
    const int*   mask   = (const int*)d_in[7];

    crf_fused_kernel<<<dim3(QB, BB), 256>>>(hidden, W, bias, stv, trv, etv,
                                            tags, mask, (float*)d_out);
}

// round 17
// speedup vs baseline: 1.2008x; 1.2008x over previous
#include <cuda_runtime.h>
#include <cstdint>

#define BB 64
#define SS 512
#define HH 768
#define CC 9
#define QB 4         // blocks per batch
#define BW 8         // warps per block
#define KCH 32       // chunks per batch (1 per warp)
#define CH 16        // steps per chunk (32*16 = 512 >= 511)
#define L2E 1.4426950408889634f
#define LN2 0.6931471805599453f
#define FULLMASK 0xffffffffu

// scratch (no allocations allowed)
__device__ __align__(16) float g_P[BB * KCH * 81];   // chunk matrices
__device__ int   g_E[BB * KCH * CC];                 // per-row exponents
__device__ float g_num[BB * KCH];                    // numerator partials
__device__ float g_emis0[BB * CC];                   // t=0 emissions
__device__ int   g_bar[BB];                          // per-batch arrivals
__device__ float g_acc = 0.0f;
__device__ int   g_cnt = 0;

__device__ __forceinline__ float ex2f(float x) {
    float y; asm("ex2.approx.ftz.f32 %0, %1;" : "=f"(y) : "f"(x)); return y;
}
__device__ __forceinline__ float lg2f(float x) {
    float y; asm("lg2.approx.ftz.f32 %0, %1;" : "=f"(y) : "f"(x)); return y;
}

// ---------------------------------------------------------------------------
// ONE kernel: grid (QB, BB) x 256. Block (q, b): 8 warps; warp w owns window
// k = q*8+w, timesteps [1+16k, 17+16k). Each warp: GEMV its 16 rows (4-row
// groups, segmented-exchange reduction: 51 SHFL vs 180) -> smem, exp -> smem,
// numerator partial, 16-step chunk product -> gmem. Last block per batch
// combines (proven lean path) + atomic mean.
// ---------------------------------------------------------------------------
__global__ __launch_bounds__(256, 2) void crf_fused_kernel(
    const float* __restrict__ hidden,
    const float* __restrict__ W,
    const float* __restrict__ bias,
    const float* __restrict__ stv,
    const float* __restrict__ trv,
    const float* __restrict__ etv,
    const int*   __restrict__ tags,
    const int*   __restrict__ mask,
    float* __restrict__ out)
{
    __shared__ alignas(16) float Wsm[CC * HH];        // 27648 B
    __shared__ alignas(16) union {
        struct {                                      // phase 1
            float raw[BW][CH * 12];                   // 6144 B raw emissions
            float eml[BW][CH * 12];                   // 6144 B exp(emissions)
        } p1;
        struct {                                      // phase 2 (combine blk)
            float P[KCH * 81];                        // 10368 B
            int   E[KCH * CC];                        // 1152 B
            int   Emax[KCH];                          // 128 B
        } p2;
    } u;
    __shared__ alignas(16) float Te_sm[CC][12];
    __shared__ float tr_sh[81];
    __shared__ float bias_sm[CC];
    __shared__ int   iam_last;

    const int q    = blockIdx.x;
    const int b    = blockIdx.y;
    const int tid  = threadIdx.x;
    const int wid  = tid >> 5;
    const int lane = tid & 31;
    const int k    = q * BW + wid;        // chunk/window id 0..31
    const int t0   = 1 + CH * k;          // first timestep of window

    for (int i = tid; i < CC * HH / 4; i += 256)
        ((float4*)Wsm)[i] = ((const float4*)W)[i];
    if (tid < 81) {
        const float t = trv[tid];
        tr_sh[tid] = t;
        Te_sm[tid / 9][tid % 9] = ex2f(t * L2E);
    }
    if (tid < CC) bias_sm[tid] = bias[tid];
    __syncthreads();

    // sequence length (mask is a prefix of ones)
    int len = 0;
    {
        const int* mrow = mask + (size_t)b * SS;
        for (int t = lane; t < SS; t += 32) len += mrow[t];
#pragma unroll
        for (int off = 16; off > 0; off >>= 1)
            len += __shfl_xor_sync(FULLMASK, len, off);
    }

    // ---- GEMV: 16 rows (+ t=0 extra group for q==0,wid==0) ----
    const int ngroups = (q == 0 && wid == 0) ? 5 : 4;
#pragma unroll 1
    for (int g = 0; g < ngroups; g++) {
        const int rbase = (g < 4) ? (t0 + 4 * g) : 0;
        const int r0 = (rbase + 0 < SS) ? rbase + 0 : SS - 1;
        const int r1 = (rbase + 1 < SS) ? rbase + 1 : SS - 1;
        const int r2 = (rbase + 2 < SS) ? rbase + 2 : SS - 1;
        const int r3 = (rbase + 3 < SS) ? rbase + 3 : SS - 1;
        const float4* hp0 = (const float4*)(hidden + ((size_t)b * SS + r0) * HH);
        const float4* hp1 = (const float4*)(hidden + ((size_t)b * SS + r1) * HH);
        const float4* hp2 = (const float4*)(hidden + ((size_t)b * SS + r2) * HH);
        const float4* hp3 = (const float4*)(hidden + ((size_t)b * SS + r3) * HH);

        float acc[4][CC];
#pragma unroll
        for (int r = 0; r < 4; r++)
#pragma unroll
            for (int c = 0; c < CC; c++) acc[r][c] = 0.0f;

#pragma unroll 3
        for (int i = 0; i < HH / 128; i++) {   // 6 iterations
            float4 h[4];
            h[0] = hp0[i * 32 + lane];
            h[1] = hp1[i * 32 + lane];
            h[2] = hp2[i * 32 + lane];
            h[3] = hp3[i * 32 + lane];
#pragma unroll
            for (int c = 0; c < CC; c++) {
                const float4 w = ((const float4*)(Wsm + c * HH))[i * 32 + lane];
#pragma unroll
                for (int r = 0; r < 4; r++) {
                    acc[r][c] = fmaf(h[r].x, w.x, acc[r][c]);
                    acc[r][c] = fmaf(h[r].y, w.y, acc[r][c]);
                    acc[r][c] = fmaf(h[r].z, w.z, acc[r][c]);
                    acc[r][c] = fmaf(h[r].w, w.w, acc[r][c]);
                }
            }
        }

        // ---- segmented-exchange reduction: 32 values (r<4, c<8) in 31 SHFL.
        // After 5 levels, lane l holds the full warp-sum of value i = l
        // (r = l>>3, c = l&7).
        float red[16];
#pragma unroll
        for (int j = 0; j < 16; j++) {
            const float lo = acc[j >> 3][j & 7];            // A[j]     (r 0..1)
            const float hi = acc[(j + 16) >> 3][j & 7];     // A[j+16]  (r 2..3)
            const float send = (lane & 16) ? lo : hi;
            const float recv = __shfl_xor_sync(FULLMASK, send, 16);
            red[j] = ((lane & 16) ? hi : lo) + recv;
        }
#pragma unroll
        for (int j = 0; j < 8; j++) {
            const float send = (lane & 8) ? red[j] : red[j + 8];
            const float recv = __shfl_xor_sync(FULLMASK, send, 8);
            red[j] = ((lane & 8) ? red[j + 8] : red[j]) + recv;
        }
#pragma unroll
        for (int j = 0; j < 4; j++) {
            const float send = (lane & 4) ? red[j] : red[j + 4];
            const float recv = __shfl_xor_sync(FULLMASK, send, 4);
            red[j] = ((lane & 4) ? red[j + 4] : red[j]) + recv;
        }
#pragma unroll
        for (int j = 0; j < 2; j++) {
            const float send = (lane & 2) ? red[j] : red[j + 2];
            const float recv = __shfl_xor_sync(FULLMASK, send, 2);
            red[j] = ((lane & 2) ? red[j + 2] : red[j]) + recv;
        }
        {
            const float send = (lane & 1) ? red[0] : red[1];
            const float recv = __shfl_xor_sync(FULLMASK, send, 1);
            red[0] = ((lane & 1) ? red[1] : red[0]) + recv;
        }
        // class 8: plain butterfly on 4 values (20 SHFL)
        float s8[4];
#pragma unroll
        for (int r = 0; r < 4; r++) {
            s8[r] = acc[r][8];
#pragma unroll
            for (int off = 16; off > 0; off >>= 1)
                s8[r] += __shfl_xor_sync(FULLMASK, s8[r], off);
        }

        if (g < 4) {
            // raw WITHOUT bias (bias added at consumption points)
            u.p1.raw[wid][(4 * g + (lane >> 3)) * 12 + (lane & 7)] = red[0];
            const float v8 = (lane == 0) ? s8[0] : (lane == 1) ? s8[1]
                           : (lane == 2) ? s8[2] : s8[3];
            if (lane < 4) u.p1.raw[wid][(4 * g + lane) * 12 + 8] = v8;
        } else {
            if (lane < 8) g_emis0[b * CC + lane] = red[0] + bias_sm[lane];
            if (lane == 0) g_emis0[b * CC + 8] = s8[0] + bias_sm[8];
        }
    }
    __syncwarp();

    // ---- exponentiate emissions (bias added here) ----
    for (int idx = lane; idx < CH * CC; idx += 32) {
        const int row = idx / CC;
        const int cc  = idx - row * CC;
        u.p1.eml[wid][row * 12 + cc] =
            ex2f((u.p1.raw[wid][row * 12 + cc] + bias_sm[cc]) * L2E);
    }
    __syncwarp();

    // ---- numerator partial over [t0, t0+16) ----
    float np = 0.0f;
    if (lane < CH) {
        const int t = t0 + lane;
        if (t < len) {
            const int tp = tags[(size_t)b * SS + t - 1];
            const int tc = tags[(size_t)b * SS + t];
            np = tr_sh[tp * CC + tc] + u.p1.raw[wid][lane * 12 + tc] + bias_sm[tc];
        }
    }
#pragma unroll
    for (int off = 16; off > 0; off >>= 1)
        np += __shfl_xor_sync(FULLMASK, np, off);
    if (lane == 0) g_num[b * KCH + k] = np;

    // ---- chunk matrix product: lane r < 9 holds row r of M ----
    const int r = (lane < CC) ? lane : 8;
    float m[CC];
#pragma unroll
    for (int c = 0; c < CC; c++) m[c] = (c == r) ? 1.0f : 0.0f;
    int esum = 0;

#pragma unroll 1
    for (int i = 0; i < CH; i++) {
        if (t0 + i >= len) break;
        const float* emlrow = &u.p1.eml[wid][i * 12];
        const float4 e0 = *(const float4*)&emlrow[0];
        const float4 e1 = *(const float4*)&emlrow[4];
        const float  e8 = emlrow[8];

        float v[CC];
#pragma unroll
        for (int c = 0; c < CC; c++) v[c] = 0.0f;
#pragma unroll
        for (int j = 0; j < CC; j++) {
            const float4 ta = *(const float4*)&Te_sm[j][0];
            const float4 tb2 = *(const float4*)&Te_sm[j][4];
            const float  t8 = Te_sm[j][8];
            const float  mj = m[j];
            v[0] = fmaf(mj, ta.x, v[0]); v[1] = fmaf(mj, ta.y, v[1]);
            v[2] = fmaf(mj, ta.z, v[2]); v[3] = fmaf(mj, ta.w, v[3]);
            v[4] = fmaf(mj, tb2.x, v[4]); v[5] = fmaf(mj, tb2.y, v[5]);
            v[6] = fmaf(mj, tb2.z, v[6]); v[7] = fmaf(mj, tb2.w, v[7]);
            v[8] = fmaf(mj, t8, v[8]);
        }
        v[0] *= e0.x; v[1] *= e0.y; v[2] *= e0.z; v[3] *= e0.w;
        v[4] *= e1.x; v[5] *= e1.y; v[6] *= e1.z; v[7] *= e1.w;
        v[8] *= e8;

        float mx01 = fmaxf(v[0], v[1]), mx23 = fmaxf(v[2], v[3]);
        float mx45 = fmaxf(v[4], v[5]), mx67 = fmaxf(v[6], v[7]);
        float mx = fmaxf(fmaxf(fmaxf(mx01, mx23), fmaxf(mx45, mx67)), v[8]);
        const int   eb  = (__float_as_int(mx) >> 23) & 0xff;
        const float pot = __int_as_float((254 - eb) << 23);
#pragma unroll
        for (int c = 0; c < CC; c++) m[c] = v[c] * pot;
        esum += eb - 127;
    }

    if (lane < CC) {
        float* dst = g_P + ((size_t)b * KCH + k) * 81 + r * 9;
#pragma unroll
        for (int c = 0; c < CC; c++) dst[c] = m[c];
        g_E[((size_t)b * KCH + k) * CC + r] = esum;
    }
    __syncthreads();

    // ---- arrival: last of the QB blocks for this batch combines ----
    if (tid == 0) {
        __threadfence();
        iam_last = (atomicAdd(&g_bar[b], 1) == QB - 1);
    }
    __syncthreads();
    if (!iam_last) return;
    if (tid == 0) __threadfence();   // acquire peers' writes
    __syncthreads();

    // ---- stage all 32 chunk matrices + exponents into smem ----
    for (int i = tid; i < KCH * 81 / 4; i += 256)
        ((float4*)u.p2.P)[i] = ((const float4*)(g_P + (size_t)b * KCH * 81))[i];
    for (int i = tid; i < KCH * CC; i += 256)
        u.p2.E[i] = g_E[(size_t)b * KCH * CC + i];
    __syncthreads();
    if (tid < KCH) {
        int e = u.p2.E[tid * CC];
#pragma unroll
        for (int r2 = 1; r2 < CC; r2++) e = max(e, u.p2.E[tid * CC + r2]);
        u.p2.Emax[tid] = e;
    }
    __syncthreads();
    if (wid != 0) return;

    // ---- combine (warp 0): a unnormalized, true alpha = a * 2^Etot ----
    const int  c  = (lane < CC) ? lane : 0;
    const bool on = (lane < CC);
    float a = on ? ex2f((stv[c] + g_emis0[b * CC + c]) * L2E) : 0.0f;
    int Etot = 0;

#pragma unroll 1
    for (int kk = 0; kk < KCH; kk++) {
        if (1 + kk * CH >= len) break;   // identity chunks beyond len

        const int emk = u.p2.Emax[kk];
        const int ej  = on ? u.p2.E[kk * CC + lane] : emk;
        const int d   = ej - emk;        // <= 0
        const float asc = (d > -126) ? a * __int_as_float((d + 127) << 23) : 0.0f;

        const float s0 = __shfl_sync(FULLMASK, asc, 0);
        const float s1 = __shfl_sync(FULLMASK, asc, 1);
        const float s2 = __shfl_sync(FULLMASK, asc, 2);
        const float s3 = __shfl_sync(FULLMASK, asc, 3);
        const float s4 = __shfl_sync(FULLMASK, asc, 4);
        const float s5 = __shfl_sync(FULLMASK, asc, 5);
        const float s6 = __shfl_sync(FULLMASK, asc, 6);
        const float s7 = __shfl_sync(FULLMASK, asc, 7);
        const float s8 = __shfl_sync(FULLMASK, asc, 8);

        const int   e0 = (((__float_as_int(s0) >> 23) & 0xff)) - 127;
        const float sc = __int_as_float((127 - e0) << 23);   // 2^{-e0}

        const float* Pk = u.p2.P + kk * 81;
        float p0 = s0 * Pk[0 * 9 + c], p1 = s1 * Pk[1 * 9 + c];
        float p2 = s2 * Pk[2 * 9 + c], p3 = s3 * Pk[3 * 9 + c];
        float p4 = s4 * Pk[4 * 9 + c], p5 = s5 * Pk[5 * 9 + c];
        float p6 = s6 * Pk[6 * 9 + c], p7 = s7 * Pk[7 * 9 + c];
        float p8 = s8 * Pk[8 * 9 + c];
        float q0 = p0 + p1, q1 = p2 + p3, q2 = p4 + p5, q3 = p6 + p7;
        const float na = ((q0 + q1) + (q2 + q3)) + p8;

        a = on ? na * sc : 0.0f;
        Etot += emk + e0;
    }

    // ---- denominator ----
    float term = on ? a * ex2f(etv[c] * L2E) : 0.0f;
#pragma unroll
    for (int off = 16; off > 0; off >>= 1)
        term += __shfl_xor_sync(FULLMASK, term, off);
    const float denom = (lg2f(term) + (float)Etot) * LN2;

    // ---- numerator assembly (32 partials = full warp) ----
    float nsum = g_num[b * KCH + lane];
#pragma unroll
    for (int off = 16; off > 0; off >>= 1)
        nsum += __shfl_xor_sync(FULLMASK, nsum, off);
    const int first = tags[(size_t)b * SS];
    const int last  = tags[(size_t)b * SS + len - 1];
    const float num = nsum + stv[first] + g_emis0[b * CC + first] + etv[last];
    const float llh = num - denom;

    if (lane == 0) {
        g_bar[b] = 0;   // reset for next graph replay
        atomicAdd(&g_acc, llh);
        __threadfence();
        const int cnt = atomicAdd(&g_cnt, 1);
        if (cnt == BB - 1) {
            __threadfence();
            const float total = atomicAdd(&g_acc, 0.0f);
            out[0] = -total * (1.0f / (float)BB);
            g_acc = 0.0f;
            g_cnt = 0;
        }
    }
}

// ---------------------------------------------------------------------------
extern "C" void kernel_launch(void* const* d_in, const int* in_sizes, int n_in,
                              void* d_out, int out_size)
{
    (void)in_sizes; (void)n_in; (void)out_size;
    const float* hidden = (const float*)d_in[0];
    const float* W      = (const float*)d_in[1];
    const float* bias   = (const float*)d_in[2];
    const float* stv    = (const float*)d_in[3];
    const float* trv    = (const float*)d_in[4];
    const float* etv    = (const float*)d_in[5];
    const int*   tags   = (const int*)d_in[6];
    const int*   mask   = (const int*)d_in[7];

    crf_fused_kernel<<<dim3(QB, BB), 256>>>(hidden, W, bias, stv, trv, etv,
                                            tags, mask, (float*)d_out);
}